// round 4
// baseline (speedup 1.0000x reference)
#include <cuda_runtime.h>

typedef unsigned long long u64;

#define T_ 1132
#define B_ 128
#define L_ 100
#define TH_ 14716
#define C_ 10
#define NW_ 16           // warps per layer-CTA
#define THREADS_ 512     // 4 lanes per batch element

// Double-buffered layer activations + per-(t,warp) progress flags.
__device__ float g_buf[2][T_][B_][16];   // [parity][t][b][padded H]
__device__ int   g_prog[T_][NW_];        // layers finished (t, warp-slice)

__device__ __forceinline__ int ld_acq(const int* p) {
    int v;
    asm volatile("ld.acquire.gpu.global.b32 %0, [%1];" : "=r"(v) : "l"(p) : "memory");
    return v;
}
__device__ __forceinline__ void st_rel(int* p, int v) {
    asm volatile("st.release.gpu.global.b32 [%0], %1;" :: "l"(p), "r"(v) : "memory");
}

__device__ __forceinline__ u64 pack2(float lo, float hi) {
    u64 d; asm("mov.b64 %0, {%1, %2};" : "=l"(d) : "f"(lo), "f"(hi)); return d;
}
__device__ __forceinline__ void unpack2(u64 v, float& lo, float& hi) {
    asm("mov.b64 {%0, %1}, %2;" : "=f"(lo), "=f"(hi) : "l"(v));
}
// two independent fp32 FMA lanes (FFMA2) — PTX-only instruction
__device__ __forceinline__ u64 fma2(u64 a, u64 b, u64 c) {
    u64 d; asm("fma.rn.f32x2 %0, %1, %2, %3;" : "=l"(d) : "l"(a), "l"(b), "l"(c)); return d;
}
__device__ __forceinline__ u64 add2(u64 a, u64 b) {
    u64 d; asm("add.rn.f32x2 %0, %1, %2;" : "=l"(d) : "l"(a), "l"(b)); return d;
}

__device__ __forceinline__ float sigf(float x) {
    return __fdividef(1.0f, 1.0f + __expf(-x));
}
__device__ __forceinline__ float tanh_f(float x) {
    float a = fabsf(x);
    float e = __expf(-2.0f * a);
    float t = __fdividef(1.0f - e, 1.0f + e);
    return copysignf(t, x);
}

__global__ void k_reset() {
    int i = blockIdx.x * blockDim.x + threadIdx.x;
    if (i < T_ * NW_) ((int*)g_prog)[i] = 0;
}

// One CTA per layer. 4 lanes per batch element (tid = 4*b + q); lane q owns
// hidden units j = 4q..4q+3 (j padded 13->16 with zero weights).
// Wavefront pipeline over t; warps fully independent (per-warp flags).
__global__ __launch_bounds__(THREADS_, 1) void k_lstm(
    const float* __restrict__ input,
    const float* __restrict__ w_ih, const float* __restrict__ w_hh,
    const float* __restrict__ b_ih, const float* __restrict__ b_hh)
{
    // Packed weights: s_w[p][j][kk] = {A[2kk], B[2kk], A[2kk+1], B[2kk+1]}
    //   p=0: x-side gates (i,f)  p=1: x-side (g,o)  p=2: h-side (i,f)  p=3: h-side (g,o)
    __shared__ __align__(16) float4 s_w[4][16][7];
    __shared__ __align__(16) float  s_b[16][4];    // {bi, bf, bg, bo} per j (padded)

    const int l   = blockIdx.x;
    const int tid = threadIdx.x;
    const int q   = tid & 3;        // lane within batch-group
    const int b   = tid >> 2;       // batch element
    const int w   = tid >> 5;       // warp id

    // --- load + pack weights (pad j>=13 and k>=13 with zeros) ---
    for (int i = tid; i < 4 * 16 * 28; i += THREADS_) {
        int p = i / 448, r = i % 448;
        int j = r / 28,  s = r % 28;
        int kk = s >> 2, e = s & 3;
        int k = 2 * kk + (e >> 1);
        int gate = ((p & 1) ? 2 : 0) + (e & 1);
        const float* src = (p < 2) ? w_ih : w_hh;
        float v = (j < 13 && k < 13) ? src[(l * 52 + gate * 13 + j) * 13 + k] : 0.0f;
        ((float*)s_w)[i] = v;
    }
    for (int i = tid; i < 64; i += THREADS_) {
        int g = i & 3, j = i >> 2;
        s_b[j][g] = (j < 13) ? (b_ih[l * 52 + g * 13 + j] + b_hh[l * 52 + g * 13 + j]) : 0.0f;
    }
    __syncthreads();

    // --- state in registers ---
    u64 xd[13], hd[13];
    float c[4], myh[4];
    #pragma unroll
    for (int k = 0; k < 13; k++) { xd[k] = 0ull; hd[k] = 0ull; }
    #pragma unroll
    for (int j = 0; j < 4; j++) { c[j] = 0.0f; myh[j] = 0.0f; }

    const int wp = l & 1;
    const int rp = wp ^ 1;
    const u64* pb = (const u64*)s_b;

    for (int t = 0; t < T_; t++) {
        // ---- obtain x(t), replicated into both f32x2 lanes ----
        if (l == 0) {
            const float* ir = &input[(b * T_ + t) * 13];
            #pragma unroll
            for (int k = 0; k < 13; k++) { float v = ir[k]; xd[k] = pack2(v, v); }
        } else {
            const int* fl = &g_prog[t][w];
            while (ld_acq(fl) < l) __nanosleep(20);
            const float4* src = (const float4*)&g_buf[rp][t][b][0];
            float4 v0 = src[0], v1 = src[1], v2 = src[2], v3 = src[3];
            xd[0]  = pack2(v0.x, v0.x); xd[1]  = pack2(v0.y, v0.y);
            xd[2]  = pack2(v0.z, v0.z); xd[3]  = pack2(v0.w, v0.w);
            xd[4]  = pack2(v1.x, v1.x); xd[5]  = pack2(v1.y, v1.y);
            xd[6]  = pack2(v1.z, v1.z); xd[7]  = pack2(v1.w, v1.w);
            xd[8]  = pack2(v2.x, v2.x); xd[9]  = pack2(v2.y, v2.y);
            xd[10] = pack2(v2.z, v2.z); xd[11] = pack2(v2.w, v2.w);
            xd[12] = pack2(v3.x, v3.x);
        }

        // ---- 4 owned hidden units: two 14-deep chains per gate pair ----
        #pragma unroll
        for (int jl = 0; jl < 4; jl++) {
            const int j = 4 * 0 + jl;  // placeholder; real index via q below
            (void)j;
        }
        #pragma unroll
        for (int jl = 0; jl < 4; jl++) {
            // j = 4*q + jl  (dynamic q, but smem indexing handles it)
            const int jj = (q << 2) + jl;
            u64 axif = pb[jj * 2];       // bias pair (bi,bf)
            u64 axgo = pb[jj * 2 + 1];   // bias pair (bg,bo)
            u64 ahif = 0ull, ahgo = 0ull;
            #pragma unroll
            for (int kk = 0; kk < 7; kk++) {
                ulonglong2 wxif = *(const ulonglong2*)&s_w[0][jj][kk];
                ulonglong2 wxgo = *(const ulonglong2*)&s_w[1][jj][kk];
                ulonglong2 whif = *(const ulonglong2*)&s_w[2][jj][kk];
                ulonglong2 whgo = *(const ulonglong2*)&s_w[3][jj][kk];
                int k0 = 2 * kk, k1 = 2 * kk + 1;
                u64 x0 = xd[k0], h0 = hd[k0];
                u64 x1 = (k1 < 13) ? xd[k1] : 0ull;
                u64 h1 = (k1 < 13) ? hd[k1] : 0ull;
                axif = fma2(wxif.x, x0, axif);
                axgo = fma2(wxgo.x, x0, axgo);
                ahif = fma2(whif.x, h0, ahif);
                ahgo = fma2(whgo.x, h0, ahgo);
                axif = fma2(wxif.y, x1, axif);
                axgo = fma2(wxgo.y, x1, axgo);
                ahif = fma2(whif.y, h1, ahif);
                ahgo = fma2(whgo.y, h1, ahgo);
            }
            u64 gif = add2(axif, ahif);
            u64 ggo = add2(axgo, ahgo);
            float ai, af, ag, ao;
            unpack2(gif, ai, af);
            unpack2(ggo, ag, ao);
            float ig = sigf(ai), fg = sigf(af), gv = tanh_f(ag), og = sigf(ao);
            float cn = fmaf(fg, c[jl], ig * gv);
            c[jl]   = cn;
            myh[jl] = og * tanh_f(cn);
        }

        // ---- all-gather 13 h values within the 4-lane batch group ----
        float hv[13];
        #pragma unroll
        for (int j = 0; j < 13; j++) {
            hv[j] = __shfl_sync(0xFFFFFFFFu, myh[j & 3], j >> 2, 4);
            hd[j] = pack2(hv[j], hv[j]);
        }

        // ---- publish: lane q writes its 16B quarter (coalesced 64B/batch) ----
        float4* dst = (float4*)&g_buf[wp][t][b][0];
        float4 out4;
        if      (q == 0) out4 = make_float4(hv[0], hv[1], hv[2],  hv[3]);
        else if (q == 1) out4 = make_float4(hv[4], hv[5], hv[6],  hv[7]);
        else if (q == 2) out4 = make_float4(hv[8], hv[9], hv[10], hv[11]);
        else             out4 = make_float4(hv[12], 0.0f, 0.0f, 0.0f);
        dst[q] = out4;

        __syncwarp();
        if ((tid & 31) == 0) st_rel(&g_prog[t][w], l + 1);
    }
}

// Final linear + softmax. One CTA per batch element.
__global__ __launch_bounds__(256) void k_cls(
    const float* __restrict__ w_lin, const float* __restrict__ b_lin,
    float* __restrict__ out)
{
    const int bb  = blockIdx.x;
    const int tid = threadIdx.x;

    float acc[C_];
    #pragma unroll
    for (int cc = 0; cc < C_; cc++) acc[cc] = 0.0f;

    for (int t = tid; t < T_; t += 256) {
        const float* xr = &g_buf[1][t][bb][0];   // layer 99 writes parity 1
        float xv[13];
        #pragma unroll
        for (int k = 0; k < 13; k++) xv[k] = xr[k];
        #pragma unroll
        for (int cc = 0; cc < C_; cc++) {
            const float* wr = &w_lin[cc * TH_ + t * 13];
            float a = acc[cc];
            #pragma unroll
            for (int k = 0; k < 13; k++) a = fmaf(xv[k], wr[k], a);
            acc[cc] = a;
        }
    }

    __shared__ float red[256];
    __shared__ float lg[C_];
    #pragma unroll 1
    for (int cc = 0; cc < C_; cc++) {
        red[tid] = acc[cc];
        __syncthreads();
        for (int st = 128; st > 0; st >>= 1) {
            if (tid < st) red[tid] += red[tid + st];
            __syncthreads();
        }
        if (tid == 0) lg[cc] = red[0] + b_lin[cc];
        __syncthreads();
    }

    if (tid == 0) {
        float m = lg[0];
        #pragma unroll
        for (int cc = 1; cc < C_; cc++) m = fmaxf(m, lg[cc]);
        float e[C_];
        float ssum = 0.0f;
        #pragma unroll
        for (int cc = 0; cc < C_; cc++) { e[cc] = __expf(lg[cc] - m); ssum += e[cc]; }
        float inv = __fdividef(1.0f, ssum);
        #pragma unroll
        for (int cc = 0; cc < C_; cc++) out[bb * C_ + cc] = e[cc] * inv;
    }
}

extern "C" void kernel_launch(void* const* d_in, const int* in_sizes, int n_in,
                              void* d_out, int out_size)
{
    const float* input = (const float*)d_in[0];
    const float* w_ih  = (const float*)d_in[1];
    const float* w_hh  = (const float*)d_in[2];
    const float* b_ih  = (const float*)d_in[3];
    const float* b_hh  = (const float*)d_in[4];
    const float* w_lin = (const float*)d_in[5];
    const float* b_lin = (const float*)d_in[6];

    k_reset<<<(T_ * NW_ + 255) / 256, 256>>>();
    k_lstm<<<L_, THREADS_>>>(input, w_ih, w_hh, b_ih, b_hh);
    k_cls<<<B_, 256>>>(w_lin, b_lin, (float*)d_out);
}

// round 5
// speedup vs baseline: 1.9040x; 1.9040x over previous
#include <cuda_runtime.h>

typedef unsigned long long u64;

#define T_ 1132
#define B_ 128
#define L_ 100
#define TH_ 14716
#define C_ 10
#define NW_ 8            // warps per layer-CTA
#define THREADS_ 256     // 2 lanes (k-split) per batch element

// Double-buffered layer activations + per-(t,warp) progress flags.
__device__ float g_buf[2][T_][B_][16];   // [parity][t][b][padded H]
__device__ int   g_prog[T_][NW_];        // layers finished (t, warp-slice)

__device__ __forceinline__ int ld_acq(const int* p) {
    int v;
    asm volatile("ld.acquire.gpu.global.b32 %0, [%1];" : "=r"(v) : "l"(p) : "memory");
    return v;
}
__device__ __forceinline__ void st_rel(int* p, int v) {
    asm volatile("st.release.gpu.global.b32 [%0], %1;" :: "l"(p), "r"(v) : "memory");
}

__device__ __forceinline__ u64 pack2(float lo, float hi) {
    u64 d; asm("mov.b64 %0, {%1, %2};" : "=l"(d) : "f"(lo), "f"(hi)); return d;
}
__device__ __forceinline__ void unpack2(u64 v, float& lo, float& hi) {
    asm("mov.b64 {%0, %1}, %2;" : "=f"(lo), "=f"(hi) : "l"(v));
}
// two independent fp32 FMA lanes (FFMA2) — PTX-only
__device__ __forceinline__ u64 fma2(u64 a, u64 b, u64 c) {
    u64 d; asm("fma.rn.f32x2 %0, %1, %2, %3;" : "=l"(d) : "l"(a), "l"(b), "l"(c)); return d;
}
__device__ __forceinline__ u64 add2(u64 a, u64 b) {
    u64 d; asm("add.rn.f32x2 %0, %1, %2;" : "=l"(d) : "l"(a), "l"(b)); return d;
}

__device__ __forceinline__ float sigf(float x) {
    return __fdividef(1.0f, 1.0f + __expf(-x));
}
// exact-form tanh via sigmoid identity: 2/(1+e^-2x) - 1 (saturates cleanly)
__device__ __forceinline__ float tanh_f(float x) {
    float s = __fdividef(2.0f, 1.0f + __expf(-2.0f * x));
    return s - 1.0f;
}

__global__ void k_reset() {
    int i = blockIdx.x * blockDim.x + threadIdx.x;
    if (i < T_ * NW_) ((int*)g_prog)[i] = 0;
}

// One CTA per layer. Lane pair per batch (tid = 2*b_local + p); lane parity p
// owns k-window [8p, 8p+8) of the (padded-16) input/hidden dim.
// Warp w covers batches [16w, 16w+16). Per-warp global flags; no CTA barriers.
__global__ __launch_bounds__(THREADS_, 1) void k_lstm(
    const float* __restrict__ input,
    const float* __restrict__ w_ih, const float* __restrict__ w_hh,
    const float* __restrict__ b_ih, const float* __restrict__ b_hh)
{
    // s_w[side][j][kk] = {A(2kk), B(2kk), A(2kk+1), B(2kk+1)}  (kk 0..7, k padded to 16)
    //   side0: x,(i,f)  side1: x,(g,o)  side2: h,(i,f)  side3: h,(g,o)
    __shared__ __align__(16) float4 s_w[4][16][8];
    __shared__ __align__(16) float  s_b[16][4];   // {bi,bf,bg,bo} per j

    const int l   = blockIdx.x;
    const int tid = threadIdx.x;
    const int p   = tid & 1;        // k-half
    const int b   = tid >> 1;       // batch element
    const int w   = tid >> 5;       // warp id

    // --- load + pack weights (zeros for j>=13 or k>=13) ---
    for (int i = tid; i < 4 * 16 * 32; i += THREADS_) {
        int side = i >> 9, r = i & 511;
        int j = r >> 5, s2 = r & 31;
        int kk = s2 >> 2, e = s2 & 3;
        int k = 2 * kk + (e >> 1);
        int gate = ((side & 1) ? 2 : 0) + (e & 1);
        const float* src = (side < 2) ? w_ih : w_hh;
        float v = (j < 13 && k < 13) ? src[(l * 52 + gate * 13 + j) * 13 + k] : 0.0f;
        ((float*)s_w)[i] = v;
    }
    for (int i = tid; i < 64; i += THREADS_) {
        int g = i & 3, j = i >> 2;
        s_b[j][g] = (j < 13) ? (b_ih[l * 52 + g * 13 + j] + b_hh[l * 52 + g * 13 + j]) : 0.0f;
    }
    __syncthreads();

    // --- per-thread state ---
    u64 xd[8], hd[8];               // lane's k-window, f32x2-replicated
    float c[7], myh[7];             // owned hidden units (p=0: j0..6, p=1: j7..12)
    #pragma unroll
    for (int k = 0; k < 8; k++) { xd[k] = 0ull; hd[k] = 0ull; }
    #pragma unroll
    for (int j = 0; j < 7; j++) { c[j] = 0.0f; myh[j] = 0.0f; }

    const int wp = l & 1;
    const int rp = wp ^ 1;
    const u64* pb = (const u64*)s_b;
    const int kbase = p << 3;

    for (int t = 0; t < T_; t++) {
        // ---- obtain x(t) for my k-half, replicated into both f32x2 lanes ----
        if (l == 0) {
            const float* ir = &input[(b * T_ + t) * 13];
            #pragma unroll
            for (int kl = 0; kl < 8; kl++) {
                int k = kbase + kl;
                float v = (k < 13) ? ir[k] : 0.0f;
                xd[kl] = pack2(v, v);
            }
        } else {
            const int* fl = &g_prog[t][w];
            while (ld_acq(fl) < l) __nanosleep(20);
            const float4* src = (const float4*)&g_buf[rp][t][b][0];
            float4 v0 = src[2 * p], v1 = src[2 * p + 1];
            xd[0] = pack2(v0.x, v0.x); xd[1] = pack2(v0.y, v0.y);
            xd[2] = pack2(v0.z, v0.z); xd[3] = pack2(v0.w, v0.w);
            xd[4] = pack2(v1.x, v1.x); xd[5] = pack2(v1.y, v1.y);
            xd[6] = pack2(v1.z, v1.z); xd[7] = pack2(v1.w, v1.w);
        }

        // ---- partial gate sums over my k-half, all 13 units ----
        u64 aif[13], ago[13];
        #pragma unroll
        for (int j = 0; j < 13; j++) {
            u64 sif = (p == 0) ? pb[j * 2]     : 0ull;   // bias seeded once
            u64 sgo = (p == 0) ? pb[j * 2 + 1] : 0ull;
            #pragma unroll
            for (int kkl = 0; kkl < 4; kkl++) {
                const int kk = kbase / 2 + kkl;          // = 4p + kkl
                ulonglong2 wxif = *(const ulonglong2*)&s_w[0][j][kk];
                ulonglong2 wxgo = *(const ulonglong2*)&s_w[1][j][kk];
                ulonglong2 whif = *(const ulonglong2*)&s_w[2][j][kk];
                ulonglong2 whgo = *(const ulonglong2*)&s_w[3][j][kk];
                u64 x0 = xd[2 * kkl], x1 = xd[2 * kkl + 1];
                u64 h0 = hd[2 * kkl], h1 = hd[2 * kkl + 1];
                sif = fma2(wxif.x, x0, sif);
                sgo = fma2(wxgo.x, x0, sgo);
                sif = fma2(whif.x, h0, sif);
                sgo = fma2(whgo.x, h0, sgo);
                sif = fma2(wxif.y, x1, sif);
                sgo = fma2(wxgo.y, x1, sgo);
                sif = fma2(whif.y, h1, sif);
                sgo = fma2(whgo.y, h1, sgo);
            }
            aif[j] = sif;
            ago[j] = sgo;
        }

        // ---- combine partner halves (bulk, independent shuffles) ----
        #pragma unroll
        for (int j = 0; j < 13; j++) {
            aif[j] = add2(aif[j], __shfl_xor_sync(0xFFFFFFFFu, aif[j], 1));
            ago[j] = add2(ago[j], __shfl_xor_sync(0xFFFFFFFFu, ago[j], 1));
        }

        // ---- activations for owned units ----
        if (p == 0) {
            #pragma unroll
            for (int jl = 0; jl < 7; jl++) {
                float ai, af, ag, ao;
                unpack2(aif[jl], ai, af);
                unpack2(ago[jl], ag, ao);
                float ig = sigf(ai), fg = sigf(af), gv = tanh_f(ag), og = sigf(ao);
                float cn = fmaf(fg, c[jl], ig * gv);
                c[jl]   = cn;
                myh[jl] = og * tanh_f(cn);
            }
        } else {
            #pragma unroll
            for (int jl = 0; jl < 6; jl++) {
                float ai, af, ag, ao;
                unpack2(aif[7 + jl], ai, af);
                unpack2(ago[7 + jl], ag, ao);
                float ig = sigf(ai), fg = sigf(af), gv = tanh_f(ag), og = sigf(ao);
                float cn = fmaf(fg, c[jl], ig * gv);
                c[jl]   = cn;
                myh[jl] = og * tanh_f(cn);
            }
        }

        // ---- all-gather 13 h values within the lane pair ----
        float hv[13];
        #pragma unroll
        for (int j = 0; j < 13; j++) {
            int owner = (j < 7) ? 0 : 1;
            int slot  = (j < 7) ? j : j - 7;
            hv[j] = __shfl_sync(0xFFFFFFFFu, myh[slot < 7 ? slot : 0], owner, 2);
        }

        // ---- repack hd for my k-window ----
        if (p == 0) {
            hd[0] = pack2(hv[0], hv[0]); hd[1] = pack2(hv[1], hv[1]);
            hd[2] = pack2(hv[2], hv[2]); hd[3] = pack2(hv[3], hv[3]);
            hd[4] = pack2(hv[4], hv[4]); hd[5] = pack2(hv[5], hv[5]);
            hd[6] = pack2(hv[6], hv[6]); hd[7] = pack2(hv[7], hv[7]);
        } else {
            hd[0] = pack2(hv[8],  hv[8]);  hd[1] = pack2(hv[9],  hv[9]);
            hd[2] = pack2(hv[10], hv[10]); hd[3] = pack2(hv[11], hv[11]);
            hd[4] = pack2(hv[12], hv[12]); hd[5] = 0ull;
            hd[6] = 0ull;                  hd[7] = 0ull;
        }

        // ---- publish my half (two 16B stores; 64B total per batch) ----
        float4* dst = (float4*)&g_buf[wp][t][b][0];
        if (p == 0) {
            dst[0] = make_float4(hv[0], hv[1], hv[2], hv[3]);
            dst[1] = make_float4(hv[4], hv[5], hv[6], hv[7]);
        } else {
            dst[2] = make_float4(hv[8], hv[9], hv[10], hv[11]);
            dst[3] = make_float4(hv[12], 0.0f, 0.0f, 0.0f);
        }

        __syncwarp();
        if ((tid & 31) == 0) st_rel(&g_prog[t][w], l + 1);
    }
}

// Final linear + softmax. One CTA per batch element.
__global__ __launch_bounds__(256) void k_cls(
    const float* __restrict__ w_lin, const float* __restrict__ b_lin,
    float* __restrict__ out)
{
    const int bb  = blockIdx.x;
    const int tid = threadIdx.x;

    float acc[C_];
    #pragma unroll
    for (int cc = 0; cc < C_; cc++) acc[cc] = 0.0f;

    for (int t = tid; t < T_; t += 256) {
        const float* xr = &g_buf[1][t][bb][0];   // layer 99 writes parity 1
        float xv[13];
        #pragma unroll
        for (int k = 0; k < 13; k++) xv[k] = xr[k];
        #pragma unroll
        for (int cc = 0; cc < C_; cc++) {
            const float* wr = &w_lin[cc * TH_ + t * 13];
            float a = acc[cc];
            #pragma unroll
            for (int k = 0; k < 13; k++) a = fmaf(xv[k], wr[k], a);
            acc[cc] = a;
        }
    }

    __shared__ float red[256];
    __shared__ float lg[C_];
    #pragma unroll 1
    for (int cc = 0; cc < C_; cc++) {
        red[tid] = acc[cc];
        __syncthreads();
        for (int st = 128; st > 0; st >>= 1) {
            if (tid < st) red[tid] += red[tid + st];
            __syncthreads();
        }
        if (tid == 0) lg[cc] = red[0] + b_lin[cc];
        __syncthreads();
    }

    if (tid == 0) {
        float m = lg[0];
        #pragma unroll
        for (int cc = 1; cc < C_; cc++) m = fmaxf(m, lg[cc]);
        float e[C_];
        float ssum = 0.0f;
        #pragma unroll
        for (int cc = 0; cc < C_; cc++) { e[cc] = __expf(lg[cc] - m); ssum += e[cc]; }
        float inv = __fdividef(1.0f, ssum);
        #pragma unroll
        for (int cc = 0; cc < C_; cc++) out[bb * C_ + cc] = e[cc] * inv;
    }
}

extern "C" void kernel_launch(void* const* d_in, const int* in_sizes, int n_in,
                              void* d_out, int out_size)
{
    const float* input = (const float*)d_in[0];
    const float* w_ih  = (const float*)d_in[1];
    const float* w_hh  = (const float*)d_in[2];
    const float* b_ih  = (const float*)d_in[3];
    const float* b_hh  = (const float*)d_in[4];
    const float* w_lin = (const float*)d_in[5];
    const float* b_lin = (const float*)d_in[6];

    k_reset<<<(T_ * NW_ + 255) / 256, 256>>>();
    k_lstm<<<L_, THREADS_>>>(input, w_ih, w_hh, b_ih, b_hh);
    k_cls<<<B_, 256>>>(w_lin, b_lin, (float*)d_out);
}

// round 6
// speedup vs baseline: 2.2599x; 1.1869x over previous
#include <cuda_runtime.h>

typedef unsigned long long u64;

#define T_ 1132
#define B_ 128
#define L_ 100
#define TH_ 14716
#define C_ 10
#define NW_ 4            // warps per layer-CTA
#define THREADS_ 128     // 1 thread per batch element

// Double-buffered layer activations + per-(t,warp) progress flags.
__device__ float g_buf[2][T_][B_][16];   // [parity][t][b][padded H]
__device__ int   g_prog[T_][NW_];        // layers finished (t, warp-slice)

__device__ __forceinline__ int ld_acq(const int* p) {
    int v;
    asm volatile("ld.acquire.gpu.global.b32 %0, [%1];" : "=r"(v) : "l"(p) : "memory");
    return v;
}
__device__ __forceinline__ void st_rel(int* p, int v) {
    asm volatile("st.release.gpu.global.b32 [%0], %1;" :: "l"(p), "r"(v) : "memory");
}

__device__ __forceinline__ u64 pack2(float lo, float hi) {
    u64 d; asm("mov.b64 %0, {%1, %2};" : "=l"(d) : "f"(lo), "f"(hi)); return d;
}
__device__ __forceinline__ void unpack2(u64 v, float& lo, float& hi) {
    asm("mov.b64 {%0, %1}, %2;" : "=f"(lo), "=f"(hi) : "l"(v));
}
// two independent fp32 FMA lanes (FFMA2) — PTX-only instruction
__device__ __forceinline__ u64 fma2(u64 a, u64 b, u64 c) {
    u64 d; asm("fma.rn.f32x2 %0, %1, %2, %3;" : "=l"(d) : "l"(a), "l"(b), "l"(c)); return d;
}
__device__ __forceinline__ u64 add2(u64 a, u64 b) {
    u64 d; asm("add.rn.f32x2 %0, %1, %2;" : "=l"(d) : "l"(a), "l"(b)); return d;
}

__device__ __forceinline__ float sigf(float x) {
    return __fdividef(1.0f, 1.0f + __expf(-x));
}
// tanh via sigmoid identity: 2/(1+e^-2x) - 1 (exact saturation, no NaN)
__device__ __forceinline__ float tanh_f(float x) {
    return __fdividef(2.0f, 1.0f + __expf(-2.0f * x)) - 1.0f;
}

__global__ void k_reset() {
    int i = blockIdx.x * blockDim.x + threadIdx.x;
    if (i < T_ * NW_) ((int*)g_prog)[i] = 0;
}

// One CTA per layer, one thread per batch element, one warp per 32-batch slice.
// Wavefront pipeline over t with 1-step prefetch of the cross-layer handoff:
// flag[t+1] acquire + x(t+1) loads are issued before cell t's compute and
// validated after it, hiding the L2 round trip under the FMA work.
__global__ __launch_bounds__(THREADS_, 1) void k_lstm(
    const float* __restrict__ input,
    const float* __restrict__ w_ih, const float* __restrict__ w_hh,
    const float* __restrict__ b_ih, const float* __restrict__ b_hh)
{
    // Packed weights: s_w[p][j][kk] = {A[2kk], B[2kk], A[2kk+1], B[2kk+1]}
    //   p=0: x-side gates (i,f)  p=1: x-side (g,o)  p=2: h-side (i,f)  p=3: h-side (g,o)
    __shared__ __align__(16) float4 s_w[4][13][7];
    __shared__ __align__(16) float  s_b[13][4];   // {bi, bf, bg, bo} per j

    const int l   = blockIdx.x;
    const int b   = threadIdx.x;
    const int w   = b >> 5;

    // --- load + pack weights ---
    for (int i = b; i < 4 * 13 * 28; i += THREADS_) {
        int p = i / 364, r = i % 364;
        int j = r / 28,  s2 = r % 28;
        int kk = s2 >> 2, e = s2 & 3;
        int k = 2 * kk + (e >> 1);
        int gate = ((p & 1) ? 2 : 0) + (e & 1);
        const float* src = (p < 2) ? w_ih : w_hh;
        float v = (k < 13) ? src[(l * 52 + gate * 13 + j) * 13 + k] : 0.0f;
        ((float*)s_w)[i] = v;
    }
    for (int i = b; i < 52; i += THREADS_) {
        int g = i / 13, j = i % 13;
        s_b[j][g] = b_ih[l * 52 + i] + b_hh[l * 52 + i];
    }
    __syncthreads();

    // --- state in registers ---
    u64 xd[13], hd[13];
    float c[13], hn[13];
    #pragma unroll
    for (int k = 0; k < 13; k++) { xd[k] = 0ull; hd[k] = 0ull; }
    #pragma unroll
    for (int j = 0; j < 13; j++) { c[j] = 0.0f; hn[j] = 0.0f; }

    const int wp = l & 1;
    const int rp = wp ^ 1;
    const u64* pb = (const u64*)s_b;

    // ---- preload x(0) ----
    if (l == 0) {
        const float* ir = &input[(b * T_ + 0) * 13];
        #pragma unroll
        for (int k = 0; k < 13; k++) { float v = ir[k]; xd[k] = pack2(v, v); }
    } else {
        while (ld_acq(&g_prog[0][w]) < l) { }
        const float4* src = (const float4*)&g_buf[rp][0][b][0];
        float4 v0 = src[0], v1 = src[1], v2 = src[2], v3 = src[3];
        xd[0]  = pack2(v0.x, v0.x); xd[1]  = pack2(v0.y, v0.y);
        xd[2]  = pack2(v0.z, v0.z); xd[3]  = pack2(v0.w, v0.w);
        xd[4]  = pack2(v1.x, v1.x); xd[5]  = pack2(v1.y, v1.y);
        xd[6]  = pack2(v1.z, v1.z); xd[7]  = pack2(v1.w, v1.w);
        xd[8]  = pack2(v2.x, v2.x); xd[9]  = pack2(v2.y, v2.y);
        xd[10] = pack2(v2.z, v2.z); xd[11] = pack2(v2.w, v2.w);
        xd[12] = pack2(v3.x, v3.x);
    }

    for (int t = 0; t < T_; t++) {
        const bool pf = (t + 1 < T_);
        int fv = 0;
        float4 n0, n1, n2, n3;
        float  nin[13];

        // ---- blind prefetch of next cell's input (overlaps compute below) ----
        if (pf) {
            if (l == 0) {
                const float* ir = &input[(b * T_ + t + 1) * 13];
                #pragma unroll
                for (int k = 0; k < 13; k++) nin[k] = ir[k];
            } else {
                fv = ld_acq(&g_prog[t + 1][w]);   // acquire orders the loads below
                const float4* src = (const float4*)&g_buf[rp][t + 1][b][0];
                n0 = src[0]; n1 = src[1]; n2 = src[2]; n3 = src[3];
            }
        }

        // ---- gates + state update (split x/h chains, fully unrolled) ----
        #pragma unroll
        for (int j = 0; j < 13; j++) {
            u64 axif = pb[j * 2];
            u64 axgo = pb[j * 2 + 1];
            u64 ahif = 0ull, ahgo = 0ull;
            #pragma unroll
            for (int kk = 0; kk < 7; kk++) {
                ulonglong2 wxif = *(const ulonglong2*)&s_w[0][j][kk];
                ulonglong2 wxgo = *(const ulonglong2*)&s_w[1][j][kk];
                ulonglong2 whif = *(const ulonglong2*)&s_w[2][j][kk];
                ulonglong2 whgo = *(const ulonglong2*)&s_w[3][j][kk];
                int k0 = 2 * kk, k1 = 2 * kk + 1;
                u64 x0 = xd[k0], h0 = hd[k0];
                u64 x1 = (k1 < 13) ? xd[k1] : 0ull;
                u64 h1 = (k1 < 13) ? hd[k1] : 0ull;
                axif = fma2(wxif.x, x0, axif);
                axgo = fma2(wxgo.x, x0, axgo);
                ahif = fma2(whif.x, h0, ahif);
                ahgo = fma2(whgo.x, h0, ahgo);
                axif = fma2(wxif.y, x1, axif);
                axgo = fma2(wxgo.y, x1, axgo);
                ahif = fma2(whif.y, h1, ahif);
                ahgo = fma2(whgo.y, h1, ahgo);
            }
            u64 gif = add2(axif, ahif);
            u64 ggo = add2(axgo, ahgo);
            float ai, af, ag, ao;
            unpack2(gif, ai, af);
            unpack2(ggo, ag, ao);
            float ig = sigf(ai), fg = sigf(af), gv = tanh_f(ag), og = sigf(ao);
            float cn = fmaf(fg, c[j], ig * gv);
            c[j]  = cn;
            hn[j] = og * tanh_f(cn);
        }

        // ---- commit h + publish to next layer ASAP ----
        #pragma unroll
        for (int j = 0; j < 13; j++) hd[j] = pack2(hn[j], hn[j]);

        float4* dst = (float4*)&g_buf[wp][t][b][0];
        dst[0] = make_float4(hn[0], hn[1], hn[2],  hn[3]);
        dst[1] = make_float4(hn[4], hn[5], hn[6],  hn[7]);
        dst[2] = make_float4(hn[8], hn[9], hn[10], hn[11]);
        g_buf[wp][t][b][12] = hn[12];

        __syncwarp();
        if ((b & 31) == 0) st_rel(&g_prog[t][w], l + 1);

        // ---- validate prefetch; fall back to poll + reload on miss ----
        if (pf) {
            if (l == 0) {
                #pragma unroll
                for (int k = 0; k < 13; k++) xd[k] = pack2(nin[k], nin[k]);
            } else {
                if (fv < l) {
                    while (ld_acq(&g_prog[t + 1][w]) < l) { }
                    const float4* src = (const float4*)&g_buf[rp][t + 1][b][0];
                    n0 = src[0]; n1 = src[1]; n2 = src[2]; n3 = src[3];
                }
                xd[0]  = pack2(n0.x, n0.x); xd[1]  = pack2(n0.y, n0.y);
                xd[2]  = pack2(n0.z, n0.z); xd[3]  = pack2(n0.w, n0.w);
                xd[4]  = pack2(n1.x, n1.x); xd[5]  = pack2(n1.y, n1.y);
                xd[6]  = pack2(n1.z, n1.z); xd[7]  = pack2(n1.w, n1.w);
                xd[8]  = pack2(n2.x, n2.x); xd[9]  = pack2(n2.y, n2.y);
                xd[10] = pack2(n2.z, n2.z); xd[11] = pack2(n2.w, n2.w);
                xd[12] = pack2(n3.x, n3.x);
            }
        }
    }
}

// Final linear + softmax. One CTA per batch element.
__global__ __launch_bounds__(256) void k_cls(
    const float* __restrict__ w_lin, const float* __restrict__ b_lin,
    float* __restrict__ out)
{
    const int bb  = blockIdx.x;
    const int tid = threadIdx.x;

    float acc[C_];
    #pragma unroll
    for (int cc = 0; cc < C_; cc++) acc[cc] = 0.0f;

    for (int t = tid; t < T_; t += 256) {
        const float* xr = &g_buf[1][t][bb][0];   // layer 99 writes parity 1
        float xv[13];
        #pragma unroll
        for (int k = 0; k < 13; k++) xv[k] = xr[k];
        #pragma unroll
        for (int cc = 0; cc < C_; cc++) {
            const float* wr = &w_lin[cc * TH_ + t * 13];
            float a = acc[cc];
            #pragma unroll
            for (int k = 0; k < 13; k++) a = fmaf(xv[k], wr[k], a);
            acc[cc] = a;
        }
    }

    __shared__ float red[256];
    __shared__ float lg[C_];
    #pragma unroll 1
    for (int cc = 0; cc < C_; cc++) {
        red[tid] = acc[cc];
        __syncthreads();
        for (int st = 128; st > 0; st >>= 1) {
            if (tid < st) red[tid] += red[tid + st];
            __syncthreads();
        }
        if (tid == 0) lg[cc] = red[0] + b_lin[cc];
        __syncthreads();
    }

    if (tid == 0) {
        float m = lg[0];
        #pragma unroll
        for (int cc = 1; cc < C_; cc++) m = fmaxf(m, lg[cc]);
        float e[C_];
        float ssum = 0.0f;
        #pragma unroll
        for (int cc = 0; cc < C_; cc++) { e[cc] = __expf(lg[cc] - m); ssum += e[cc]; }
        float inv = __fdividef(1.0f, ssum);
        #pragma unroll
        for (int cc = 0; cc < C_; cc++) out[bb * C_ + cc] = e[cc] * inv;
    }
}

extern "C" void kernel_launch(void* const* d_in, const int* in_sizes, int n_in,
                              void* d_out, int out_size)
{
    const float* input = (const float*)d_in[0];
    const float* w_ih  = (const float*)d_in[1];
    const float* w_hh  = (const float*)d_in[2];
    const float* b_ih  = (const float*)d_in[3];
    const float* b_hh  = (const float*)d_in[4];
    const float* w_lin = (const float*)d_in[5];
    const float* b_lin = (const float*)d_in[6];

    // Flags are zero at module load; k_reset (last) re-zeros them after each
    // call, so every invocation (and every graph replay) starts from zeros.
    // k_lstm first also puts it in ncu's captured launch slot.
    k_lstm<<<L_, THREADS_>>>(input, w_ih, w_hh, b_ih, b_hh);
    k_cls<<<B_, 256>>>(w_lin, b_lin, (float*)d_out);
    k_reset<<<(T_ * NW_ + 255) / 256, 256>>>();
}

// round 8
// speedup vs baseline: 2.3320x; 1.0319x over previous
#include <cuda_runtime.h>

typedef unsigned long long u64;

#define T_ 1132
#define B_ 128
#define L_ 100
#define TH_ 14716
#define C_ 10
#define NW_ 8            // warps per layer-CTA
#define THREADS_ 256     // 2 lanes (j-split) per batch element

// Double-buffered layer activations + per-(t,warp) progress flags.
__device__ float g_buf[2][T_][B_][16];   // [parity][t][b][padded H]
__device__ int   g_prog[T_][NW_];        // layers finished (t, warp-slice)

__device__ __forceinline__ int ld_acq(const int* p) {
    int v;
    asm volatile("ld.acquire.gpu.global.b32 %0, [%1];" : "=r"(v) : "l"(p) : "memory");
    return v;
}
__device__ __forceinline__ void st_rel(int* p, int v) {
    asm volatile("st.release.gpu.global.b32 [%0], %1;" :: "l"(p), "r"(v) : "memory");
}

__device__ __forceinline__ u64 pack2(float lo, float hi) {
    u64 d; asm("mov.b64 %0, {%1, %2};" : "=l"(d) : "f"(lo), "f"(hi)); return d;
}
__device__ __forceinline__ void unpack2(u64 v, float& lo, float& hi) {
    asm("mov.b64 {%0, %1}, %2;" : "=f"(lo), "=f"(hi) : "l"(v));
}
// two independent fp32 FMA lanes (FFMA2) — PTX-only instruction
__device__ __forceinline__ u64 fma2(u64 a, u64 b, u64 c) {
    u64 d; asm("fma.rn.f32x2 %0, %1, %2, %3;" : "=l"(d) : "l"(a), "l"(b), "l"(c)); return d;
}
__device__ __forceinline__ u64 add2(u64 a, u64 b) {
    u64 d; asm("add.rn.f32x2 %0, %1, %2;" : "=l"(d) : "l"(a), "l"(b)); return d;
}

__device__ __forceinline__ float sigf(float x) {
    return __fdividef(1.0f, 1.0f + __expf(-x));
}
// tanh via sigmoid identity: 2/(1+e^-2x) - 1 (clean saturation, no NaN)
__device__ __forceinline__ float tanh_f(float x) {
    return __fdividef(2.0f, 1.0f + __expf(-2.0f * x)) - 1.0f;
}

__global__ void k_reset() {
    int i = blockIdx.x * blockDim.x + threadIdx.x;
    if (i < T_ * NW_) ((int*)g_prog)[i] = 0;
}

// One CTA per layer. Lane pair per batch (tid = 2*b_local + p); lane parity p
// owns hidden units j in [7p, 7p+7) (j padded to 14 with zero weights, so the
// unrolled loop is uniform; lane 1's 7th unit is inert). Full x/h per lane,
// so gates need NO cross-lane reduction; h is all-gathered with 13 width-2
// shuffles. 1-step prefetch of the cross-layer handoff hides the L2 trip.
__global__ __launch_bounds__(THREADS_, 1) void k_lstm(
    const float* __restrict__ input,
    const float* __restrict__ w_ih, const float* __restrict__ w_hh,
    const float* __restrict__ b_ih, const float* __restrict__ b_hh)
{
    // Packed weights, j padded to 14:
    // s_w[side][j][kk] = {A[2kk], B[2kk], A[2kk+1], B[2kk+1]}
    //   side0: x,(i,f)  side1: x,(g,o)  side2: h,(i,f)  side3: h,(g,o)
    __shared__ __align__(16) float4 s_w[4][14][7];
    __shared__ __align__(16) float  s_b[14][4];   // {bi, bf, bg, bo} per j

    const int l   = blockIdx.x;
    const int tid = threadIdx.x;
    const int p   = tid & 1;        // j-half owner
    const int b   = tid >> 1;       // batch element
    const int w   = tid >> 5;       // warp id

    // --- load + pack weights (zeros for j>=13 or k>=13) ---
    for (int i = tid; i < 4 * 14 * 28; i += THREADS_) {
        int side = i / 392, r = i % 392;
        int j = r / 28,  s2 = r % 28;
        int kk = s2 >> 2, e = s2 & 3;
        int k = 2 * kk + (e >> 1);
        int gate = ((side & 1) ? 2 : 0) + (e & 1);
        const float* src = (side < 2) ? w_ih : w_hh;
        float v = (j < 13 && k < 13) ? src[(l * 52 + gate * 13 + j) * 13 + k] : 0.0f;
        ((float*)s_w)[i] = v;
    }
    for (int i = tid; i < 56; i += THREADS_) {
        int g = i & 3, j = i >> 2;
        s_b[j][g] = (j < 13) ? (b_ih[l * 52 + g * 13 + j] + b_hh[l * 52 + g * 13 + j]) : 0.0f;
    }
    __syncthreads();

    // --- per-thread state ---
    u64 xd[13], hd[13];             // full x/h, f32x2-replicated
    float c[7], myh[7];             // owned hidden units
    #pragma unroll
    for (int k = 0; k < 13; k++) { xd[k] = 0ull; hd[k] = 0ull; }
    #pragma unroll
    for (int j = 0; j < 7; j++) { c[j] = 0.0f; myh[j] = 0.0f; }

    const int wp = l & 1;
    const int rp = wp ^ 1;
    const u64* pb = (const u64*)s_b;
    const int jbase = 7 * p;

    // ---- preload x(0) ----
    if (l == 0) {
        const float* ir = &input[(b * T_ + 0) * 13];
        #pragma unroll
        for (int k = 0; k < 13; k++) { float v = ir[k]; xd[k] = pack2(v, v); }
    } else {
        while (ld_acq(&g_prog[0][w]) < l) { }
        const float4* src = (const float4*)&g_buf[rp][0][b][0];
        float4 v0 = src[0], v1 = src[1], v2 = src[2], v3 = src[3];
        xd[0]  = pack2(v0.x, v0.x); xd[1]  = pack2(v0.y, v0.y);
        xd[2]  = pack2(v0.z, v0.z); xd[3]  = pack2(v0.w, v0.w);
        xd[4]  = pack2(v1.x, v1.x); xd[5]  = pack2(v1.y, v1.y);
        xd[6]  = pack2(v1.z, v1.z); xd[7]  = pack2(v1.w, v1.w);
        xd[8]  = pack2(v2.x, v2.x); xd[9]  = pack2(v2.y, v2.y);
        xd[10] = pack2(v2.z, v2.z); xd[11] = pack2(v2.w, v2.w);
        xd[12] = pack2(v3.x, v3.x);
    }

    for (int t = 0; t < T_; t++) {
        const bool pf = (t + 1 < T_);
        int fv = 0;
        float4 n0, n1, n2, n3;
        float  nin[13];

        // ---- blind prefetch of next cell's input (overlaps compute) ----
        if (pf) {
            if (l == 0) {
                const float* ir = &input[(b * T_ + t + 1) * 13];
                #pragma unroll
                for (int k = 0; k < 13; k++) nin[k] = ir[k];
            } else {
                fv = ld_acq(&g_prog[t + 1][w]);   // acquire orders loads below
                const float4* src = (const float4*)&g_buf[rp][t + 1][b][0];
                n0 = src[0]; n1 = src[1]; n2 = src[2]; n3 = src[3];
            }
        }

        // ---- gates + state update for my 7 owned units ----
        #pragma unroll
        for (int jl = 0; jl < 7; jl++) {
            const int jj = jbase + jl;           // p=1, jl=6 -> jj=13 (inert pad)
            u64 axif = pb[jj * 2];
            u64 axgo = pb[jj * 2 + 1];
            u64 ahif = 0ull, ahgo = 0ull;
            #pragma unroll
            for (int kk = 0; kk < 7; kk++) {
                ulonglong2 wxif = *(const ulonglong2*)&s_w[0][jj][kk];
                ulonglong2 wxgo = *(const ulonglong2*)&s_w[1][jj][kk];
                ulonglong2 whif = *(const ulonglong2*)&s_w[2][jj][kk];
                ulonglong2 whgo = *(const ulonglong2*)&s_w[3][jj][kk];
                int k0 = 2 * kk, k1 = 2 * kk + 1;
                u64 x0 = xd[k0], h0 = hd[k0];
                u64 x1 = (k1 < 13) ? xd[k1] : 0ull;
                u64 h1 = (k1 < 13) ? hd[k1] : 0ull;
                axif = fma2(wxif.x, x0, axif);
                axgo = fma2(wxgo.x, x0, axgo);
                ahif = fma2(whif.x, h0, ahif);
                ahgo = fma2(whgo.x, h0, ahgo);
                axif = fma2(wxif.y, x1, axif);
                axgo = fma2(wxgo.y, x1, axgo);
                ahif = fma2(whif.y, h1, ahif);
                ahgo = fma2(whgo.y, h1, ahgo);
            }
            u64 gif = add2(axif, ahif);
            u64 ggo = add2(axgo, ahgo);
            float ai, af, ag, ao;
            unpack2(gif, ai, af);
            unpack2(ggo, ag, ao);
            float ig = sigf(ai), fg = sigf(af), gv = tanh_f(ag), og = sigf(ao);
            float cn = fmaf(fg, c[jl], ig * gv);
            c[jl]   = cn;
            myh[jl] = og * tanh_f(cn);
        }

        // ---- all-gather 13 h values within the lane pair ----
        float hv[13];
        #pragma unroll
        for (int j = 0; j < 13; j++) {
            const int owner = (j < 7) ? 0 : 1;
            const int slot  = (j < 7) ? j : j - 7;
            hv[j] = __shfl_sync(0xFFFFFFFFu, myh[slot], owner, 2);
            hd[j] = pack2(hv[j], hv[j]);
        }

        // ---- publish my half (two 16B stores; 64B total per batch) ----
        float4* dst = (float4*)&g_buf[wp][t][b][0];
        if (p == 0) {
            dst[0] = make_float4(hv[0], hv[1], hv[2], hv[3]);
            dst[1] = make_float4(hv[4], hv[5], hv[6], hv[7]);
        } else {
            dst[2] = make_float4(hv[8], hv[9], hv[10], hv[11]);
            dst[3] = make_float4(hv[12], 0.0f, 0.0f, 0.0f);
        }

        __syncwarp();
        if ((tid & 31) == 0) st_rel(&g_prog[t][w], l + 1);

        // ---- validate prefetch; fall back to poll + reload on miss ----
        if (pf) {
            if (l == 0) {
                #pragma unroll
                for (int k = 0; k < 13; k++) xd[k] = pack2(nin[k], nin[k]);
            } else {
                if (fv < l) {
                    while (ld_acq(&g_prog[t + 1][w]) < l) { }
                    const float4* src = (const float4*)&g_buf[rp][t + 1][b][0];
                    n0 = src[0]; n1 = src[1]; n2 = src[2]; n3 = src[3];
                }
                xd[0]  = pack2(n0.x, n0.x); xd[1]  = pack2(n0.y, n0.y);
                xd[2]  = pack2(n0.z, n0.z); xd[3]  = pack2(n0.w, n0.w);
                xd[4]  = pack2(n1.x, n1.x); xd[5]  = pack2(n1.y, n1.y);
                xd[6]  = pack2(n1.z, n1.z); xd[7]  = pack2(n1.w, n1.w);
                xd[8]  = pack2(n2.x, n2.x); xd[9]  = pack2(n2.y, n2.y);
                xd[10] = pack2(n2.z, n2.z); xd[11] = pack2(n2.w, n2.w);
                xd[12] = pack2(n3.x, n3.x);
            }
        }
    }
}

// Final linear + softmax. One CTA per batch element.
__global__ __launch_bounds__(256) void k_cls(
    const float* __restrict__ w_lin, const float* __restrict__ b_lin,
    float* __restrict__ out)
{
    const int bb  = blockIdx.x;
    const int tid = threadIdx.x;

    float acc[C_];
    #pragma unroll
    for (int cc = 0; cc < C_; cc++) acc[cc] = 0.0f;

    for (int t = tid; t < T_; t += 256) {
        const float* xr = &g_buf[1][t][bb][0];   // layer 99 writes parity 1
        float xv[13];
        #pragma unroll
        for (int k = 0; k < 13; k++) xv[k] = xr[k];
        #pragma unroll
        for (int cc = 0; cc < C_; cc++) {
            const float* wr = &w_lin[cc * TH_ + t * 13];
            float a = acc[cc];
            #pragma unroll
            for (int k = 0; k < 13; k++) a = fmaf(xv[k], wr[k], a);
            acc[cc] = a;
        }
    }

    __shared__ float red[256];
    __shared__ float lg[C_];
    #pragma unroll 1
    for (int cc = 0; cc < C_; cc++) {
        red[tid] = acc[cc];
        __syncthreads();
        for (int st = 128; st > 0; st >>= 1) {
            if (tid < st) red[tid] += red[tid + st];
            __syncthreads();
        }
        if (tid == 0) lg[cc] = red[0] + b_lin[cc];
        __syncthreads();
    }

    if (tid == 0) {
        float m = lg[0];
        #pragma unroll
        for (int cc = 1; cc < C_; cc++) m = fmaxf(m, lg[cc]);
        float e[C_];
        float ssum = 0.0f;
        #pragma unroll
        for (int cc = 0; cc < C_; cc++) { e[cc] = __expf(lg[cc] - m); ssum += e[cc]; }
        float inv = __fdividef(1.0f, ssum);
        #pragma unroll
        for (int cc = 0; cc < C_; cc++) out[bb * C_ + cc] = e[cc] * inv;
    }
}

extern "C" void kernel_launch(void* const* d_in, const int* in_sizes, int n_in,
                              void* d_out, int out_size)
{
    const float* input = (const float*)d_in[0];
    const float* w_ih  = (const float*)d_in[1];
    const float* w_hh  = (const float*)d_in[2];
    const float* b_ih  = (const float*)d_in[3];
    const float* b_hh  = (const float*)d_in[4];
    const float* w_lin = (const float*)d_in[5];
    const float* b_lin = (const float*)d_in[6];

    // Flags zero at module load; k_reset (last) re-zeros after each call so
    // every graph replay starts clean. k_lstm first keeps it in ncu's slot.
    k_lstm<<<L_, THREADS_>>>(input, w_ih, w_hh, b_ih, b_hh);
    k_cls<<<B_, 256>>>(w_lin, b_lin, (float*)d_out);
    k_reset<<<(T_ * NW_ + 255) / 256, 256>>>();
}